// round 5
// baseline (speedup 1.0000x reference)
#include <cuda_runtime.h>
#include <cstdint>

// ---------------------------------------------------------------------------
// PCT position-embedding + 4 offset-attention SA layers. B=8, C=256, D=64,
// N=2048. tf32 mma.sync everywhere (operands pre-rounded rna).
// Softmax is never materialized: a rowstats pass computes {rowmax, 1/rowsum},
// and the xr GEMM applies exp on load, fusing colsum + h - xr/colsum.
// ---------------------------------------------------------------------------

#define B_   8
#define C_   256
#define D_   64
#define N_   2048

__device__ float  g_pos [B_ * C_ * N_];
__device__ float  g_h0  [B_ * C_ * N_];
__device__ float  g_h1  [B_ * C_ * N_];
__device__ float  g_hp  [B_ * C_ * N_];
__device__ float  g_xrnd[B_ * C_ * N_];
__device__ float  g_q   [B_ * D_ * N_];
__device__ float  g_qT  [B_ * N_ * D_];
__device__ float  g_val [B_ * C_ * N_];
__device__ float  g_d   [B_ * C_ * N_];
__device__ float  g_att [(long long)B_ * N_ * N_];
__device__ float2 g_rstat[B_ * N_];
__device__ float  g_wts [655360];

__device__ __forceinline__ float rna_tf32(float x) {
    uint32_t u;
    asm("cvt.rna.tf32.f32 %0, %1;" : "=r"(u) : "f"(x));
    return __uint_as_float(u);
}
__device__ __forceinline__ uint32_t smem_u32(const void* p) {
    return (uint32_t)__cvta_generic_to_shared(p);
}

// ---------------------------------------------------------------------------
// shared warp-tile compute: 8x(16x8x8) tf32 mma, warp tile 64x32
// ---------------------------------------------------------------------------
__device__ __forceinline__ void compute_tile(
    const float (*Asb)[20], const float (*Bsb)[136],
    float acc[4][4][4], int lane, int wm0, int wn0, int g, int tg)
{
#pragma unroll
    for (int ks = 0; ks < 2; ks++) {
        uint32_t a[4][4];
#pragma unroll
        for (int mt = 0; mt < 4; mt++) {
            const float* pa = &Asb[wm0 + mt * 16 + (lane & 15)][ks * 8 + (lane >> 4) * 4];
            uint32_t ad = smem_u32(pa);
            asm volatile("ldmatrix.sync.aligned.m8n8.x4.shared.b16 {%0,%1,%2,%3}, [%4];"
                : "=r"(a[mt][0]), "=r"(a[mt][1]), "=r"(a[mt][2]), "=r"(a[mt][3])
                : "r"(ad));
        }
        uint32_t bf[4][2];
#pragma unroll
        for (int nt = 0; nt < 4; nt++) {
            bf[nt][0] = __float_as_uint(Bsb[ks * 8 + tg    ][wn0 + nt * 8 + g]);
            bf[nt][1] = __float_as_uint(Bsb[ks * 8 + tg + 4][wn0 + nt * 8 + g]);
        }
#pragma unroll
        for (int mt = 0; mt < 4; mt++)
#pragma unroll
            for (int nt = 0; nt < 4; nt++) {
                asm volatile(
                    "mma.sync.aligned.m16n8k8.row.col.f32.tf32.tf32.f32 "
                    "{%0,%1,%2,%3}, {%4,%5,%6,%7}, {%8,%9}, {%0,%1,%2,%3};"
                    : "+f"(acc[mt][nt][0]), "+f"(acc[mt][nt][1]),
                      "+f"(acc[mt][nt][2]), "+f"(acc[mt][nt][3])
                    : "r"(a[mt][0]), "r"(a[mt][1]), "r"(a[mt][2]), "r"(a[mt][3]),
                      "r"(bf[nt][0]), "r"(bf[nt][1]));
            }
    }
}

// ---------------------------------------------------------------------------
// prep kernel: rounds all weights + x, computes pos.
// ---------------------------------------------------------------------------
#define SEG_W1   65536L
#define SEG_QV   327680L
#define SEG_WT   262144L
#define SEG_X    ((long)B_ * C_ * N_)
#define PREP_TOT (SEG_W1 + SEG_QV + SEG_WT + SEG_X + SEG_X)

__global__ void prep_kernel(const float* __restrict__ conv1_w,
                            const float* __restrict__ Wqk,
                            const float* __restrict__ Wv,
                            const float* __restrict__ Wt,
                            const float* __restrict__ x,
                            const float* __restrict__ convpos,
                            const float* __restrict__ xyz)
{
    long i = (long)blockIdx.x * 256 + threadIdx.x;
    if (i >= PREP_TOT) return;
    if (i < SEG_W1) {
        g_wts[i] = rna_tf32(conv1_w[i]);
    } else if (i < SEG_W1 + SEG_QV) {
        long j = i - SEG_W1;
        int layer = (int)(j / 81920);
        long o = j % 81920;
        float v = (o < 16384) ? Wqk[(long)layer * 16384 + o]
                              : Wv[(long)layer * 65536 + (o - 16384)];
        g_wts[i] = rna_tf32(v);
    } else if (i < SEG_W1 + SEG_QV + SEG_WT) {
        g_wts[i] = rna_tf32(Wt[i - SEG_W1 - SEG_QV]);
    } else if (i < SEG_W1 + SEG_QV + SEG_WT + SEG_X) {
        long j = i - SEG_W1 - SEG_QV - SEG_WT;
        g_xrnd[j] = rna_tf32(x[j]);
    } else {
        long j = i - SEG_W1 - SEG_QV - SEG_WT - SEG_X;
        int n = (int)(j % N_);
        int c = (int)((j / N_) % C_);
        int b = (int)(j / ((long)C_ * N_));
        const float* pp = xyz + ((long)b * N_ + n) * 3;
        g_pos[j] = convpos[c * 3 + 0] * pp[0] + convpos[c * 3 + 1] * pp[1]
                 + convpos[c * 3 + 2] * pp[2];
    }
}

// ---------------------------------------------------------------------------
// legacy tf32 GEMM (conv1 / qval / energy / t-update epilogues)
// ---------------------------------------------------------------------------
enum { EPI_BN_RELU = 0, EPI_QVAL = 1, EPI_PLAIN = 2, EPI_T_UPDATE = 4 };

template <int EPI>
__global__ void __launch_bounds__(256, 2)
tgemm(const float* __restrict__ A, long aStride, int M, int K,
      const float* __restrict__ Bm, long bStride,
      float* __restrict__ Cm, long cStride,
      const float* __restrict__ bias,
      const float* __restrict__ bng, const float* __restrict__ bnb,
      const float* __restrict__ bnm, const float* __restrict__ bnv,
      const float* __restrict__ hres, long hresStride,
      const float* __restrict__ posB,
      float* __restrict__ hpOut,
      float* __restrict__ out2, long out2Stride,
      float* __restrict__ qB, float* __restrict__ qTB)
{
    __shared__ float As[2][128][20];
    __shared__ float Bs[2][16][136];

    const int bz = blockIdx.z;
    const float* Ab = A + (long)bz * aStride;
    const float* Bb = Bm + (long)bz * bStride;

    const int m0 = blockIdx.y * 128;
    const int n0 = blockIdx.x * 128;
    const int t  = threadIdx.x;
    const int lane = t & 31;
    const int w    = t >> 5;
    const int g  = lane >> 2, tg = lane & 3;
    const int wm0 = (w >> 2) * 64, wn0 = (w & 3) * 32;

    float acc[4][4][4];
#pragma unroll
    for (int i = 0; i < 4; i++)
#pragma unroll
        for (int j = 0; j < 4; j++)
#pragma unroll
            for (int k = 0; k < 4; k++) acc[i][j][k] = 0.f;

    const int aR0 = t >> 2,  aC = (t & 3) * 4;
    const int bR0 = t >> 5,  bC = (t & 31) * 4;
    const int nStages = K >> 4;

    {
#pragma unroll
        for (int h = 0; h < 2; h++) {
            int row = aR0 + h * 64;
            if (m0 + row < M) {
                uint32_t dst = smem_u32(&As[0][row][aC]);
                const float* src = Ab + (long)(m0 + row) * K + aC;
                asm volatile("cp.async.cg.shared.global [%0], [%1], 16;" :: "r"(dst), "l"(src));
            }
        }
#pragma unroll
        for (int h = 0; h < 2; h++) {
            int row = bR0 + h * 8;
            uint32_t dst = smem_u32(&Bs[0][row][bC]);
            const float* src = Bb + (long)row * N_ + n0 + bC;
            asm volatile("cp.async.cg.shared.global [%0], [%1], 16;" :: "r"(dst), "l"(src));
        }
        asm volatile("cp.async.commit_group;");
    }
    for (int s = 0; s < nStages; s++) {
        const int cur = s & 1;
        if (s + 1 < nStages) {
            const int k0 = (s + 1) * 16, buf = (s + 1) & 1;
#pragma unroll
            for (int h = 0; h < 2; h++) {
                int row = aR0 + h * 64;
                if (m0 + row < M) {
                    uint32_t dst = smem_u32(&As[buf][row][aC]);
                    const float* src = Ab + (long)(m0 + row) * K + k0 + aC;
                    asm volatile("cp.async.cg.shared.global [%0], [%1], 16;" :: "r"(dst), "l"(src));
                }
            }
#pragma unroll
            for (int h = 0; h < 2; h++) {
                int row = bR0 + h * 8;
                uint32_t dst = smem_u32(&Bs[buf][row][bC]);
                const float* src = Bb + (long)(k0 + row) * N_ + n0 + bC;
                asm volatile("cp.async.cg.shared.global [%0], [%1], 16;" :: "r"(dst), "l"(src));
            }
        }
        asm volatile("cp.async.commit_group;");
        asm volatile("cp.async.wait_group 1;");
        __syncthreads();
        compute_tile(As[cur], Bs[cur], acc, lane, wm0, wn0, g, tg);
        __syncthreads();
    }

    float* Cb = Cm + (long)bz * cStride;
#pragma unroll
    for (int mt = 0; mt < 4; mt++) {
#pragma unroll
        for (int half = 0; half < 2; half++) {
            const int r = m0 + wm0 + mt * 16 + g + half * 8;
            if (r >= M) continue;

            float sc = 1.f, sh = 0.f, bsv = 0.f;
            if (EPI == EPI_BN_RELU || EPI == EPI_T_UPDATE) {
                float inv = rsqrtf(bnv[r] + 1e-5f);
                sc = bng[r] * inv; sh = bnb[r] - bnm[r] * sc;
            }
            if (EPI == EPI_T_UPDATE) bsv = bias[r];
            if (EPI == EPI_QVAL && r >= 64) bsv = bias[r - 64];

#pragma unroll
            for (int nt = 0; nt < 4; nt++) {
                const int cb = n0 + wn0 + nt * 8 + 2 * tg;
                float v0 = acc[mt][nt][half * 2 + 0];
                float v1 = acc[mt][nt][half * 2 + 1];
                long rowoff = (long)r * N_ + cb;

                if (EPI == EPI_BN_RELU) {
                    v0 = fmaxf(fmaf(v0, sc, sh), 0.f);
                    v1 = fmaxf(fmaf(v1, sc, sh), 0.f);
                    *reinterpret_cast<float2*>(Cb + rowoff) = make_float2(v0, v1);
                    const float* pb = posB + (long)bz * hresStride;
                    float2 p2 = *reinterpret_cast<const float2*>(pb + rowoff);
                    float* hbp = hpOut + (long)bz * hresStride;
                    *reinterpret_cast<float2*>(hbp + rowoff) =
                        make_float2(rna_tf32(v0 + p2.x), rna_tf32(v1 + p2.y));
                } else if (EPI == EPI_QVAL) {
                    if (r < 64) {
                        float q0 = rna_tf32(v0), q1 = rna_tf32(v1);
                        float* qb = qB + (long)bz * ((long)D_ * N_);
                        *reinterpret_cast<float2*>(qb + (long)r * N_ + cb) = make_float2(q0, q1);
                        float* qt = qTB + (long)bz * ((long)N_ * D_);
                        qt[(long)cb * D_ + r]       = q0;
                        qt[(long)(cb + 1) * D_ + r] = q1;
                    } else {
                        long vo = (long)(r - 64) * N_ + cb;
                        *reinterpret_cast<float2*>(Cb + vo) =
                            make_float2(rna_tf32(v0 + bsv), rna_tf32(v1 + bsv));
                    }
                } else if (EPI == EPI_PLAIN) {
                    *reinterpret_cast<float2*>(Cb + rowoff) = make_float2(v0, v1);
                } else { // EPI_T_UPDATE
                    v0 = fmaxf(fmaf(v0 + bsv, sc, sh), 0.f);
                    v1 = fmaxf(fmaf(v1 + bsv, sc, sh), 0.f);
                    const float* hb = hres + (long)bz * hresStride;
                    float2 h2 = *reinterpret_cast<const float2*>(hb + rowoff);
                    float o0 = v0 + h2.x, o1 = v1 + h2.y;
                    *reinterpret_cast<float2*>(Cb + rowoff) = make_float2(o0, o1);
                    float* ob = out2 + (long)bz * out2Stride;
                    *reinterpret_cast<float2*>(ob + rowoff) = make_float2(o0, o1);
                    const float* pb = posB + (long)bz * hresStride;
                    float2 p2 = *reinterpret_cast<const float2*>(pb + rowoff);
                    float* hb2 = hpOut + (long)bz * hresStride;
                    *reinterpret_cast<float2*>(hb2 + rowoff) =
                        make_float2(rna_tf32(o0 + p2.x), rna_tf32(o1 + p2.y));
                }
            }
        }
    }
}

// ---------------------------------------------------------------------------
// rowstats: per attention row, {max, 1/sum(exp(e - max))}. att left raw.
// ---------------------------------------------------------------------------
__global__ void __launch_bounds__(256)
rowstats_kernel(const float* __restrict__ E, float2* __restrict__ rstat)
{
    long row = blockIdx.x;
    const float4* r = reinterpret_cast<const float4*>(E + row * (long)N_);
    const int t = threadIdx.x;

    float4 va = r[t];
    float4 vb = r[t + 256];
    float mx = fmaxf(fmaxf(fmaxf(va.x, va.y), fmaxf(va.z, va.w)),
                     fmaxf(fmaxf(vb.x, vb.y), fmaxf(vb.z, vb.w)));

    __shared__ float red[8];
#pragma unroll
    for (int o = 16; o > 0; o >>= 1) mx = fmaxf(mx, __shfl_xor_sync(0xffffffffu, mx, o));
    if ((t & 31) == 0) red[t >> 5] = mx;
    __syncthreads();
    float bm = red[0];
#pragma unroll
    for (int w = 1; w < 8; w++) bm = fmaxf(bm, red[w]);
    __syncthreads();

    float sum = __expf(va.x - bm) + __expf(va.y - bm) + __expf(va.z - bm) + __expf(va.w - bm)
              + __expf(vb.x - bm) + __expf(vb.y - bm) + __expf(vb.z - bm) + __expf(vb.w - bm);
#pragma unroll
    for (int o = 16; o > 0; o >>= 1) sum += __shfl_xor_sync(0xffffffffu, sum, o);
    if ((t & 31) == 0) red[t >> 5] = sum;
    __syncthreads();
    if (t == 0) {
        float tot = 0.f;
#pragma unroll
        for (int w = 0; w < 8; w++) tot += red[w];
        rstat[row] = make_float2(bm, 1.f / tot);
    }
}

// ---------------------------------------------------------------------------
// xr kernel: d[c, m] = rna( h[c, m] - (val @ softmax_att)[c, m] / colsum[m] )
// Full M=256 c-tile per block (512 threads, 16 warps), att read ONCE.
// B tile built on the fly: p = rna(exp(e - rmax[n]) * invsum[n]); colsum fused.
// ---------------------------------------------------------------------------
#define XRS_AS   0
#define XRS_BS   40960
#define XRS_CS   58368
#define XRS_CSB  66560
#define XRS_SMEM 67072

__global__ void __launch_bounds__(512, 1)
xr_kernel(const float* __restrict__ val, const float* __restrict__ e,
          const float2* __restrict__ rstat,
          const float* __restrict__ hres, float* __restrict__ dout)
{
    extern __shared__ char sm[];
    float (*As)[256][20] = reinterpret_cast<float(*)[256][20]>(sm + XRS_AS);
    float (*Bs)[16][136] = reinterpret_cast<float(*)[16][136]>(sm + XRS_BS);
    float (*csred)[128]  = reinterpret_cast<float(*)[128]>(sm + XRS_CS);
    float* csb           = reinterpret_cast<float*>(sm + XRS_CSB);

    const int bz = blockIdx.z;
    const int m0 = blockIdx.x * 128;
    const float*  valb = val   + (long)bz * C_ * N_;
    const float*  eb   = e     + (long)bz * (long)N_ * N_;
    const float2* rsb  = rstat + (long)bz * N_;
    const float*  hb   = hres  + (long)bz * C_ * N_;
    float*        db   = dout  + (long)bz * C_ * N_;

    const int t = threadIdx.x, lane = t & 31, w = t >> 5;
    const int g = lane >> 2, tg = lane & 3;
    const int wm0 = (w >> 2) * 64, wn0 = (w & 3) * 32;

    float acc[4][4][4];
#pragma unroll
    for (int i = 0; i < 4; i++)
#pragma unroll
        for (int j = 0; j < 4; j++)
#pragma unroll
            for (int k = 0; k < 4; k++) acc[i][j][k] = 0.f;

    float csum[4] = {0.f, 0.f, 0.f, 0.f};

    const int bRow = t >> 5;          // 0..15 (k-row within stage)
    const int bCol = lane * 4;        // 0..124
    const int nStages = N_ / 16;      // 128

    // prologue: A stage 0 via cp.async, B stage 0 via LDG into regs
    float4 bpre = *reinterpret_cast<const float4*>(eb + (long)bRow * N_ + m0 + bCol);
#pragma unroll
    for (int hh = 0; hh < 2; hh++) {
        int idx = t + 512 * hh;
        int row = idx >> 2, c = (idx & 3) * 4;
        uint32_t dst = smem_u32(&As[0][row][c]);
        const float* src = valb + (long)row * N_ + c;
        asm volatile("cp.async.cg.shared.global [%0], [%1], 16;" :: "r"(dst), "l"(src));
    }
    asm volatile("cp.async.commit_group;");

    for (int s = 0; s < nStages; s++) {
        const int buf = s & 1;
        const int k0 = s * 16;

        // transform stage s B regs -> smem (exp + rna + colsum)
        {
            float2 rs = rsb[k0 + bRow];
            float4 pv;
            pv.x = rna_tf32(__expf(bpre.x - rs.x) * rs.y);
            pv.y = rna_tf32(__expf(bpre.y - rs.x) * rs.y);
            pv.z = rna_tf32(__expf(bpre.z - rs.x) * rs.y);
            pv.w = rna_tf32(__expf(bpre.w - rs.x) * rs.y);
            csum[0] += pv.x; csum[1] += pv.y; csum[2] += pv.z; csum[3] += pv.w;
            *reinterpret_cast<float4*>(&Bs[buf][bRow][bCol]) = pv;
        }

        // prefetch stage s+1
        if (s + 1 < nStages) {
            const int k1 = k0 + 16;
#pragma unroll
            for (int hh = 0; hh < 2; hh++) {
                int idx = t + 512 * hh;
                int row = idx >> 2, c = (idx & 3) * 4;
                uint32_t dst = smem_u32(&As[buf ^ 1][row][c]);
                const float* src = valb + (long)row * N_ + k1 + c;
                asm volatile("cp.async.cg.shared.global [%0], [%1], 16;" :: "r"(dst), "l"(src));
            }
            bpre = *reinterpret_cast<const float4*>(eb + (long)(k1 + bRow) * N_ + m0 + bCol);
        }
        asm volatile("cp.async.commit_group;");
        asm volatile("cp.async.wait_group 1;");   // A[buf] (stage s) ready
        __syncthreads();

        compute_tile(As[buf], Bs[buf], acc, lane, wm0, wn0, g, tg);
        __syncthreads();
    }

    // colsum reduction -> csb[m] = 1/(1e-9 + colsum)
    csred[bRow][bCol + 0] = csum[0];
    csred[bRow][bCol + 1] = csum[1];
    csred[bRow][bCol + 2] = csum[2];
    csred[bRow][bCol + 3] = csum[3];
    __syncthreads();
    if (t < 128) {
        float ssum = 0.f;
#pragma unroll
        for (int r = 0; r < 16; r++) ssum += csred[r][t];
        csb[t] = 1.f / (1e-9f + ssum);
    }
    __syncthreads();

    // epilogue: d = rna(h - acc * csb)
#pragma unroll
    for (int mt = 0; mt < 4; mt++) {
#pragma unroll
        for (int half = 0; half < 2; half++) {
            const int r = wm0 + mt * 16 + g + half * 8;   // 0..255
#pragma unroll
            for (int nt = 0; nt < 4; nt++) {
                const int cb = wn0 + nt * 8 + 2 * tg;     // 0..127
                float v0 = acc[mt][nt][half * 2 + 0];
                float v1 = acc[mt][nt][half * 2 + 1];
                long off = (long)r * N_ + m0 + cb;
                float2 h2 = *reinterpret_cast<const float2*>(hb + off);
                *reinterpret_cast<float2*>(db + off) = make_float2(
                    rna_tf32(h2.x - v0 * csb[cb]),
                    rna_tf32(h2.y - v1 * csb[cb + 1]));
            }
        }
    }
}

// ---------------------------------------------------------------------------
extern "C" void kernel_launch(void* const* d_in, const int* in_sizes, int n_in,
                              void* d_out, int out_size)
{
    (void)in_sizes; (void)n_in; (void)out_size;

    const float* x       = (const float*)d_in[0];
    const float* xyz     = (const float*)d_in[1];
    const float* conv1_w = (const float*)d_in[2];
    const float* convpos = (const float*)d_in[3];
    const float* bn1_g   = (const float*)d_in[4];
    const float* bn1_b   = (const float*)d_in[5];
    const float* bn1_m   = (const float*)d_in[6];
    const float* bn1_v   = (const float*)d_in[7];
    const float* Wqk     = (const float*)d_in[8];
    const float* Wv      = (const float*)d_in[9];
    const float* bv      = (const float*)d_in[10];
    const float* Wt      = (const float*)d_in[11];
    const float* bt      = (const float*)d_in[12];
    const float* bng     = (const float*)d_in[13];
    const float* bnb     = (const float*)d_in[14];
    const float* bnm     = (const float*)d_in[15];
    const float* bnv     = (const float*)d_in[16];
    float* out = (float*)d_out;

    float *pos, *h0, *h1, *hp, *xrnd, *q, *qT, *val, *dbuf, *att, *wts;
    float2* rstat;
    cudaGetSymbolAddress((void**)&pos,   g_pos);
    cudaGetSymbolAddress((void**)&h0,    g_h0);
    cudaGetSymbolAddress((void**)&h1,    g_h1);
    cudaGetSymbolAddress((void**)&hp,    g_hp);
    cudaGetSymbolAddress((void**)&xrnd,  g_xrnd);
    cudaGetSymbolAddress((void**)&q,     g_q);
    cudaGetSymbolAddress((void**)&qT,    g_qT);
    cudaGetSymbolAddress((void**)&val,   g_val);
    cudaGetSymbolAddress((void**)&dbuf,  g_d);
    cudaGetSymbolAddress((void**)&att,   g_att);
    cudaGetSymbolAddress((void**)&wts,   g_wts);
    cudaGetSymbolAddress((void**)&rstat, g_rstat);

    cudaFuncSetAttribute(xr_kernel,
                         cudaFuncAttributeMaxDynamicSharedMemorySize, XRS_SMEM);

    const long SCN = (long)C_ * N_;
    const long SDN = (long)D_ * N_;
    const long SNN = (long)N_ * N_;
    const long SND = (long)N_ * D_;

    float* w_conv1 = wts;
    float* w_qv    = wts + SEG_W1;
    float* w_t     = wts + SEG_W1 + SEG_QV;

    dim3 blk(256);
    dim3 gC (N_ / 128, 2, B_);
    dim3 gQV(N_ / 128, 3, B_);
    dim3 gE (N_ / 128, N_ / 128, B_);
    dim3 gXR(N_ / 128, 1, B_);

    prep_kernel<<<(int)((PREP_TOT + 255) / 256), blk>>>(conv1_w, Wqk, Wv, Wt, x,
                                                        convpos, xyz);

    tgemm<EPI_BN_RELU><<<gC, blk>>>(
        w_conv1, 0, C_, C_, xrnd, SCN, h0, SCN,
        nullptr, bn1_g, bn1_b, bn1_m, bn1_v,
        nullptr, SCN, pos, hp, nullptr, 0, nullptr, nullptr);

    float* hcur = h0;
    float* hnxt = h1;

    for (int i = 0; i < 4; i++) {
        tgemm<EPI_QVAL><<<gQV, blk>>>(
            w_qv + (long)i * 81920, 0, 320, C_, hp, SCN, val, SCN,
            bv + i * C_, nullptr, nullptr, nullptr, nullptr,
            nullptr, SCN, nullptr, nullptr, nullptr, 0, q, qT);

        tgemm<EPI_PLAIN><<<gE, blk>>>(
            qT, SND, N_, D_, q, SDN, att, SNN,
            nullptr, nullptr, nullptr, nullptr, nullptr,
            nullptr, SCN, nullptr, nullptr, nullptr, 0, nullptr, nullptr);

        rowstats_kernel<<<B_ * N_, blk>>>(att, rstat);

        xr_kernel<<<gXR, dim3(512), XRS_SMEM>>>(val, att, rstat, hcur, dbuf);

        tgemm<EPI_T_UPDATE><<<gC, blk>>>(
            w_t + (long)i * C_ * C_, 0, C_, C_, dbuf, SCN, hnxt, SCN,
            bt + i * C_, bng + i * C_, bnb + i * C_, bnm + i * C_, bnv + i * C_,
            hcur, SCN, pos, hp,
            out + (long)i * C_ * N_, (long)4 * C_ * N_, nullptr, nullptr);

        float* tmp = hcur; hcur = hnxt; hnxt = tmp;
    }
}

// round 6
// speedup vs baseline: 1.1722x; 1.1722x over previous
#include <cuda_runtime.h>
#include <cstdint>

// ---------------------------------------------------------------------------
// PCT position-embedding + 4 offset-attention SA layers. B=8, C=256, D=64,
// N=2048. tf32 mma.sync (operands pre-rounded rna). 4-stage cp.async ring
// with a single barrier per k-stage.
// ---------------------------------------------------------------------------

#define B_   8
#define C_   256
#define D_   64
#define N_   2048

__device__ float g_pos [B_ * C_ * N_];
__device__ float g_h0  [B_ * C_ * N_];
__device__ float g_h1  [B_ * C_ * N_];
__device__ float g_hp  [B_ * C_ * N_];
__device__ float g_xrnd[B_ * C_ * N_];
__device__ float g_q   [B_ * D_ * N_];
__device__ float g_qT  [B_ * N_ * D_];
__device__ float g_val [B_ * C_ * N_];
__device__ float g_d   [B_ * C_ * N_];
__device__ float g_att [(long long)B_ * N_ * N_];
__device__ float g_wts [655360];

__device__ __forceinline__ float rna_tf32(float x) {
    uint32_t u;
    asm("cvt.rna.tf32.f32 %0, %1;" : "=r"(u) : "f"(x));
    return __uint_as_float(u);
}
__device__ __forceinline__ uint32_t smem_u32(const void* p) {
    return (uint32_t)__cvta_generic_to_shared(p);
}

// ---------------------------------------------------------------------------
// warp-tile compute: 8x(16x8x8) tf32 mma, warp tile 64x32
// ---------------------------------------------------------------------------
__device__ __forceinline__ void compute_tile(
    const float (*Asb)[20], const float (*Bsb)[136],
    float acc[4][4][4], int lane, int wm0, int wn0, int g, int tg)
{
#pragma unroll
    for (int ks = 0; ks < 2; ks++) {
        uint32_t a[4][4];
#pragma unroll
        for (int mt = 0; mt < 4; mt++) {
            const float* pa = &Asb[wm0 + mt * 16 + (lane & 15)][ks * 8 + (lane >> 4) * 4];
            uint32_t ad = smem_u32(pa);
            asm volatile("ldmatrix.sync.aligned.m8n8.x4.shared.b16 {%0,%1,%2,%3}, [%4];"
                : "=r"(a[mt][0]), "=r"(a[mt][1]), "=r"(a[mt][2]), "=r"(a[mt][3])
                : "r"(ad));
        }
        uint32_t bf[4][2];
#pragma unroll
        for (int nt = 0; nt < 4; nt++) {
            bf[nt][0] = __float_as_uint(Bsb[ks * 8 + tg    ][wn0 + nt * 8 + g]);
            bf[nt][1] = __float_as_uint(Bsb[ks * 8 + tg + 4][wn0 + nt * 8 + g]);
        }
#pragma unroll
        for (int mt = 0; mt < 4; mt++)
#pragma unroll
            for (int nt = 0; nt < 4; nt++) {
                asm volatile(
                    "mma.sync.aligned.m16n8k8.row.col.f32.tf32.tf32.f32 "
                    "{%0,%1,%2,%3}, {%4,%5,%6,%7}, {%8,%9}, {%0,%1,%2,%3};"
                    : "+f"(acc[mt][nt][0]), "+f"(acc[mt][nt][1]),
                      "+f"(acc[mt][nt][2]), "+f"(acc[mt][nt][3])
                    : "r"(a[mt][0]), "r"(a[mt][1]), "r"(a[mt][2]), "r"(a[mt][3]),
                      "r"(bf[nt][0]), "r"(bf[nt][1]));
            }
    }
}

// ---------------------------------------------------------------------------
// prep kernel: rounds all weights + x, computes pos.
// ---------------------------------------------------------------------------
#define SEG_W1   65536L
#define SEG_QV   327680L
#define SEG_WT   262144L
#define SEG_X    ((long)B_ * C_ * N_)
#define PREP_TOT (SEG_W1 + SEG_QV + SEG_WT + SEG_X + SEG_X)

__global__ void prep_kernel(const float* __restrict__ conv1_w,
                            const float* __restrict__ Wqk,
                            const float* __restrict__ Wv,
                            const float* __restrict__ Wt,
                            const float* __restrict__ x,
                            const float* __restrict__ convpos,
                            const float* __restrict__ xyz)
{
    long i = (long)blockIdx.x * 256 + threadIdx.x;
    if (i >= PREP_TOT) return;
    if (i < SEG_W1) {
        g_wts[i] = rna_tf32(conv1_w[i]);
    } else if (i < SEG_W1 + SEG_QV) {
        long j = i - SEG_W1;
        int layer = (int)(j / 81920);
        long o = j % 81920;
        float v = (o < 16384) ? Wqk[(long)layer * 16384 + o]
                              : Wv[(long)layer * 65536 + (o - 16384)];
        g_wts[i] = rna_tf32(v);
    } else if (i < SEG_W1 + SEG_QV + SEG_WT) {
        g_wts[i] = rna_tf32(Wt[i - SEG_W1 - SEG_QV]);
    } else if (i < SEG_W1 + SEG_QV + SEG_WT + SEG_X) {
        long j = i - SEG_W1 - SEG_QV - SEG_WT;
        g_xrnd[j] = rna_tf32(x[j]);
    } else {
        long j = i - SEG_W1 - SEG_QV - SEG_WT - SEG_X;
        int n = (int)(j % N_);
        int c = (int)((j / N_) % C_);
        int b = (int)(j / ((long)C_ * N_));
        const float* pp = xyz + ((long)b * N_ + n) * 3;
        g_pos[j] = convpos[c * 3 + 0] * pp[0] + convpos[c * 3 + 1] * pp[1]
                 + convpos[c * 3 + 2] * pp[2];
    }
}

// ---------------------------------------------------------------------------
// tf32 GEMM, 4-stage cp.async ring, one barrier per stage.
// ---------------------------------------------------------------------------
enum { EPI_BN_RELU = 0, EPI_QVAL = 1, EPI_PLAIN = 2, EPI_COLSCALE = 3,
       EPI_T_UPDATE = 4 };

#define TG_STAGES   4
#define TG_AS_STR   (128 * 20)             // floats per A stage
#define TG_BS_STR   (16 * 136)             // floats per B stage
#define TG_CS_OFF   (TG_STAGES * (TG_AS_STR + TG_BS_STR))
#define TG_SMEM     ((TG_CS_OFF + 8 * 128 + 128) * 4)

template <int EPI>
__global__ void __launch_bounds__(256, 2)
tgemm(const float* __restrict__ A, long aStride, int M, int K,
      const float* __restrict__ Bm, long bStride,
      float* __restrict__ Cm, long cStride,
      const float* __restrict__ bias,
      const float* __restrict__ bng, const float* __restrict__ bnb,
      const float* __restrict__ bnm, const float* __restrict__ bnv,
      const float* __restrict__ hres, long hresStride,
      const float* __restrict__ posB,
      float* __restrict__ hpOut,
      float* __restrict__ out2, long out2Stride,
      float* __restrict__ qB, float* __restrict__ qTB)
{
    extern __shared__ float smd[];
    float (*As)[128][20] = reinterpret_cast<float(*)[128][20]>(smd);
    float (*Bs)[16][136] = reinterpret_cast<float(*)[16][136]>(smd + TG_STAGES * TG_AS_STR);
    float (*csred)[128]  = reinterpret_cast<float(*)[128]>(smd + TG_CS_OFF);
    float* csb           = smd + TG_CS_OFF + 8 * 128;

    const int bz = blockIdx.z;
    const float* Ab = A + (long)bz * aStride;
    const float* Bb = Bm + (long)bz * bStride;

    const int m0 = blockIdx.y * 128;
    const int n0 = blockIdx.x * 128;
    const int t  = threadIdx.x;
    const int lane = t & 31;
    const int w    = t >> 5;
    const int g  = lane >> 2, tg = lane & 3;
    const int wm0 = (w >> 2) * 64, wn0 = (w & 3) * 32;

    float acc[4][4][4];
#pragma unroll
    for (int i = 0; i < 4; i++)
#pragma unroll
        for (int j = 0; j < 4; j++)
#pragma unroll
            for (int k = 0; k < 4; k++) acc[i][j][k] = 0.f;

    float csum[4] = {0.f, 0.f, 0.f, 0.f};

    const int aR0 = t >> 2,  aC = (t & 3) * 4;
    const int bR0 = t >> 5,  bC = (t & 31) * 4;
    const int nStages = K >> 4;

    // prologue: stages 0..min(3, nStages)-1
    const int npro = (nStages < TG_STAGES - 1) ? nStages : (TG_STAGES - 1);
    for (int s = 0; s < npro; s++) {
        const int k0 = s * 16;
#pragma unroll
        for (int h = 0; h < 2; h++) {
            int row = aR0 + h * 64;
            if (m0 + row < M) {
                uint32_t dst = smem_u32(&As[s][row][aC]);
                const float* src = Ab + (long)(m0 + row) * K + k0 + aC;
                asm volatile("cp.async.cg.shared.global [%0], [%1], 16;" :: "r"(dst), "l"(src));
            }
        }
#pragma unroll
        for (int h = 0; h < 2; h++) {
            int row = bR0 + h * 8;
            uint32_t dst = smem_u32(&Bs[s][row][bC]);
            const float* src = Bb + (long)(k0 + row) * N_ + n0 + bC;
            asm volatile("cp.async.cg.shared.global [%0], [%1], 16;" :: "r"(dst), "l"(src));
        }
        asm volatile("cp.async.commit_group;");
    }

    for (int s = 0; s < nStages; s++) {
        const int buf = s & (TG_STAGES - 1);
        asm volatile("cp.async.wait_group %0;" :: "n"(TG_STAGES - 2));
        __syncthreads();   // stage s visible to all; all warps done with stage s-1

        // issue stage s+3 into buffer (s+3)&3 == (s-1)&3 (safe after barrier)
        const int sn = s + TG_STAGES - 1;
        if (sn < nStages) {
            const int k0 = sn * 16, nb = sn & (TG_STAGES - 1);
#pragma unroll
            for (int h = 0; h < 2; h++) {
                int row = aR0 + h * 64;
                if (m0 + row < M) {
                    uint32_t dst = smem_u32(&As[nb][row][aC]);
                    const float* src = Ab + (long)(m0 + row) * K + k0 + aC;
                    asm volatile("cp.async.cg.shared.global [%0], [%1], 16;" :: "r"(dst), "l"(src));
                }
            }
#pragma unroll
            for (int h = 0; h < 2; h++) {
                int row = bR0 + h * 8;
                uint32_t dst = smem_u32(&Bs[nb][row][bC]);
                const float* src = Bb + (long)(k0 + row) * N_ + n0 + bC;
                asm volatile("cp.async.cg.shared.global [%0], [%1], 16;" :: "r"(dst), "l"(src));
            }
        }
        asm volatile("cp.async.commit_group;");

        if (EPI == EPI_COLSCALE) {
#pragma unroll
            for (int h = 0; h < 2; h++) {
                const float4 v = *reinterpret_cast<const float4*>(&Bs[buf][bR0 + h * 8][bC]);
                csum[0] += v.x; csum[1] += v.y; csum[2] += v.z; csum[3] += v.w;
            }
        }
        compute_tile(As[buf], Bs[buf], acc, lane, wm0, wn0, g, tg);
    }

    if (EPI == EPI_COLSCALE) {
        __syncthreads();
        csred[t >> 5][(t & 31) * 4 + 0] = csum[0];
        csred[t >> 5][(t & 31) * 4 + 1] = csum[1];
        csred[t >> 5][(t & 31) * 4 + 2] = csum[2];
        csred[t >> 5][(t & 31) * 4 + 3] = csum[3];
        __syncthreads();
        if (t < 128) {
            float ssum = 0.f;
#pragma unroll
            for (int r = 0; r < 8; r++) ssum += csred[r][t];
            csb[t] = 1.f / (1e-9f + ssum);
        }
        __syncthreads();
    }

    float* Cb = Cm + (long)bz * cStride;
#pragma unroll
    for (int mt = 0; mt < 4; mt++) {
#pragma unroll
        for (int half = 0; half < 2; half++) {
            const int r = m0 + wm0 + mt * 16 + g + half * 8;
            if (r >= M) continue;

            float sc = 1.f, sh = 0.f, bsv = 0.f;
            if (EPI == EPI_BN_RELU || EPI == EPI_T_UPDATE) {
                float inv = rsqrtf(bnv[r] + 1e-5f);
                sc = bng[r] * inv; sh = bnb[r] - bnm[r] * sc;
            }
            if (EPI == EPI_T_UPDATE) bsv = bias[r];
            if (EPI == EPI_QVAL && r >= 64) bsv = bias[r - 64];

#pragma unroll
            for (int nt = 0; nt < 4; nt++) {
                const int cb = n0 + wn0 + nt * 8 + 2 * tg;
                float v0 = acc[mt][nt][half * 2 + 0];
                float v1 = acc[mt][nt][half * 2 + 1];
                long rowoff = (long)r * N_ + cb;

                if (EPI == EPI_BN_RELU) {
                    v0 = fmaxf(fmaf(v0, sc, sh), 0.f);
                    v1 = fmaxf(fmaf(v1, sc, sh), 0.f);
                    *reinterpret_cast<float2*>(Cb + rowoff) = make_float2(v0, v1);
                    const float* pb = posB + (long)bz * hresStride;
                    float2 p2 = *reinterpret_cast<const float2*>(pb + rowoff);
                    float* hbp = hpOut + (long)bz * hresStride;
                    *reinterpret_cast<float2*>(hbp + rowoff) =
                        make_float2(rna_tf32(v0 + p2.x), rna_tf32(v1 + p2.y));
                } else if (EPI == EPI_QVAL) {
                    if (r < 64) {
                        float q0 = rna_tf32(v0), q1 = rna_tf32(v1);
                        float* qb = qB + (long)bz * ((long)D_ * N_);
                        *reinterpret_cast<float2*>(qb + (long)r * N_ + cb) = make_float2(q0, q1);
                        float* qt = qTB + (long)bz * ((long)N_ * D_);
                        qt[(long)cb * D_ + r]       = q0;
                        qt[(long)(cb + 1) * D_ + r] = q1;
                    } else {
                        long vo = (long)(r - 64) * N_ + cb;
                        *reinterpret_cast<float2*>(Cb + vo) =
                            make_float2(rna_tf32(v0 + bsv), rna_tf32(v1 + bsv));
                    }
                } else if (EPI == EPI_PLAIN) {
                    *reinterpret_cast<float2*>(Cb + rowoff) = make_float2(v0, v1);
                } else if (EPI == EPI_COLSCALE) {
                    float i0 = csb[cb - n0], i1 = csb[cb - n0 + 1];
                    const float* hb = hres + (long)bz * hresStride;
                    float2 h2 = *reinterpret_cast<const float2*>(hb + rowoff);
                    *reinterpret_cast<float2*>(Cb + rowoff) =
                        make_float2(rna_tf32(h2.x - v0 * i0), rna_tf32(h2.y - v1 * i1));
                } else { // EPI_T_UPDATE
                    v0 = fmaxf(fmaf(v0 + bsv, sc, sh), 0.f);
                    v1 = fmaxf(fmaf(v1 + bsv, sc, sh), 0.f);
                    const float* hb = hres + (long)bz * hresStride;
                    float2 h2 = *reinterpret_cast<const float2*>(hb + rowoff);
                    float o0 = v0 + h2.x, o1 = v1 + h2.y;
                    *reinterpret_cast<float2*>(Cb + rowoff) = make_float2(o0, o1);
                    float* ob = out2 + (long)bz * out2Stride;
                    *reinterpret_cast<float2*>(ob + rowoff) = make_float2(o0, o1);
                    const float* pb = posB + (long)bz * hresStride;
                    float2 p2 = *reinterpret_cast<const float2*>(pb + rowoff);
                    float* hb2 = hpOut + (long)bz * hresStride;
                    *reinterpret_cast<float2*>(hb2 + rowoff) =
                        make_float2(rna_tf32(o0 + p2.x), rna_tf32(o1 + p2.y));
                }
            }
        }
    }
}

// ---------------------------------------------------------------------------
// Row softmax (in place), float4 + __expf, writes tf32-rounded values.
// ---------------------------------------------------------------------------
__global__ void __launch_bounds__(256)
softmax_kernel(float* __restrict__ E)
{
    long row = blockIdx.x;
    float4* r = reinterpret_cast<float4*>(E + row * (long)N_);
    const int t = threadIdx.x;

    float4 va = r[t];
    float4 vb = r[t + 256];
    float mx = fmaxf(fmaxf(fmaxf(va.x, va.y), fmaxf(va.z, va.w)),
                     fmaxf(fmaxf(vb.x, vb.y), fmaxf(vb.z, vb.w)));

    __shared__ float red[8];
#pragma unroll
    for (int o = 16; o > 0; o >>= 1) mx = fmaxf(mx, __shfl_xor_sync(0xffffffffu, mx, o));
    if ((t & 31) == 0) red[t >> 5] = mx;
    __syncthreads();
    float bm = red[0];
#pragma unroll
    for (int w = 1; w < 8; w++) bm = fmaxf(bm, red[w]);
    __syncthreads();

    va.x = __expf(va.x - bm); va.y = __expf(va.y - bm);
    va.z = __expf(va.z - bm); va.w = __expf(va.w - bm);
    vb.x = __expf(vb.x - bm); vb.y = __expf(vb.y - bm);
    vb.z = __expf(vb.z - bm); vb.w = __expf(vb.w - bm);
    float sum = va.x + va.y + va.z + va.w + vb.x + vb.y + vb.z + vb.w;
#pragma unroll
    for (int o = 16; o > 0; o >>= 1) sum += __shfl_xor_sync(0xffffffffu, sum, o);
    if ((t & 31) == 0) red[t >> 5] = sum;
    __syncthreads();
    float tot = 0.f;
#pragma unroll
    for (int w = 0; w < 8; w++) tot += red[w];

    float inv = 1.f / tot;
    va.x = rna_tf32(va.x * inv); va.y = rna_tf32(va.y * inv);
    va.z = rna_tf32(va.z * inv); va.w = rna_tf32(va.w * inv);
    vb.x = rna_tf32(vb.x * inv); vb.y = rna_tf32(vb.y * inv);
    vb.z = rna_tf32(vb.z * inv); vb.w = rna_tf32(vb.w * inv);
    r[t] = va;
    r[t + 256] = vb;
}

// ---------------------------------------------------------------------------
extern "C" void kernel_launch(void* const* d_in, const int* in_sizes, int n_in,
                              void* d_out, int out_size)
{
    (void)in_sizes; (void)n_in; (void)out_size;

    const float* x       = (const float*)d_in[0];
    const float* xyz     = (const float*)d_in[1];
    const float* conv1_w = (const float*)d_in[2];
    const float* convpos = (const float*)d_in[3];
    const float* bn1_g   = (const float*)d_in[4];
    const float* bn1_b   = (const float*)d_in[5];
    const float* bn1_m   = (const float*)d_in[6];
    const float* bn1_v   = (const float*)d_in[7];
    const float* Wqk     = (const float*)d_in[8];
    const float* Wv      = (const float*)d_in[9];
    const float* bv      = (const float*)d_in[10];
    const float* Wt      = (const float*)d_in[11];
    const float* bt      = (const float*)d_in[12];
    const float* bng     = (const float*)d_in[13];
    const float* bnb     = (const float*)d_in[14];
    const float* bnm     = (const float*)d_in[15];
    const float* bnv     = (const float*)d_in[16];
    float* out = (float*)d_out;

    float *pos, *h0, *h1, *hp, *xrnd, *q, *qT, *val, *dbuf, *att, *wts;
    cudaGetSymbolAddress((void**)&pos,  g_pos);
    cudaGetSymbolAddress((void**)&h0,   g_h0);
    cudaGetSymbolAddress((void**)&h1,   g_h1);
    cudaGetSymbolAddress((void**)&hp,   g_hp);
    cudaGetSymbolAddress((void**)&xrnd, g_xrnd);
    cudaGetSymbolAddress((void**)&q,    g_q);
    cudaGetSymbolAddress((void**)&qT,   g_qT);
    cudaGetSymbolAddress((void**)&val,  g_val);
    cudaGetSymbolAddress((void**)&dbuf, g_d);
    cudaGetSymbolAddress((void**)&att,  g_att);
    cudaGetSymbolAddress((void**)&wts,  g_wts);

    cudaFuncSetAttribute(tgemm<EPI_BN_RELU>,  cudaFuncAttributeMaxDynamicSharedMemorySize, TG_SMEM);
    cudaFuncSetAttribute(tgemm<EPI_QVAL>,     cudaFuncAttributeMaxDynamicSharedMemorySize, TG_SMEM);
    cudaFuncSetAttribute(tgemm<EPI_PLAIN>,    cudaFuncAttributeMaxDynamicSharedMemorySize, TG_SMEM);
    cudaFuncSetAttribute(tgemm<EPI_COLSCALE>, cudaFuncAttributeMaxDynamicSharedMemorySize, TG_SMEM);
    cudaFuncSetAttribute(tgemm<EPI_T_UPDATE>, cudaFuncAttributeMaxDynamicSharedMemorySize, TG_SMEM);

    const long SCN = (long)C_ * N_;
    const long SDN = (long)D_ * N_;
    const long SNN = (long)N_ * N_;
    const long SND = (long)N_ * D_;

    float* w_conv1 = wts;
    float* w_qv    = wts + SEG_W1;
    float* w_t     = wts + SEG_W1 + SEG_QV;

    dim3 blk(256);
    dim3 gC (N_ / 128, 2, B_);
    dim3 gQV(N_ / 128, 3, B_);
    dim3 gE (N_ / 128, N_ / 128, B_);

    prep_kernel<<<(int)((PREP_TOT + 255) / 256), blk>>>(conv1_w, Wqk, Wv, Wt, x,
                                                        convpos, xyz);

    tgemm<EPI_BN_RELU><<<gC, blk, TG_SMEM>>>(
        w_conv1, 0, C_, C_, xrnd, SCN, h0, SCN,
        nullptr, bn1_g, bn1_b, bn1_m, bn1_v,
        nullptr, SCN, pos, hp, nullptr, 0, nullptr, nullptr);

    float* hcur = h0;
    float* hnxt = h1;

    for (int i = 0; i < 4; i++) {
        tgemm<EPI_QVAL><<<gQV, blk, TG_SMEM>>>(
            w_qv + (long)i * 81920, 0, 320, C_, hp, SCN, val, SCN,
            bv + i * C_, nullptr, nullptr, nullptr, nullptr,
            nullptr, SCN, nullptr, nullptr, nullptr, 0, q, qT);

        tgemm<EPI_PLAIN><<<gE, blk, TG_SMEM>>>(
            qT, SND, N_, D_, q, SDN, att, SNN,
            nullptr, nullptr, nullptr, nullptr, nullptr,
            nullptr, SCN, nullptr, nullptr, nullptr, 0, nullptr, nullptr);

        softmax_kernel<<<B_ * N_, blk>>>(att);

        tgemm<EPI_COLSCALE><<<gC, blk, TG_SMEM>>>(
            val, SCN, C_, N_, att, SNN, dbuf, SCN,
            nullptr, nullptr, nullptr, nullptr, nullptr,
            hcur, SCN, nullptr, nullptr, nullptr, 0, nullptr, nullptr);

        tgemm<EPI_T_UPDATE><<<gC, blk, TG_SMEM>>>(
            w_t + (long)i * C_ * C_, 0, C_, C_, dbuf, SCN, hnxt, SCN,
            bt + i * C_, bng + i * C_, bnb + i * C_, bnm + i * C_, bnv + i * C_,
            hcur, SCN, pos, hp,
            out + (long)i * C_ * N_, (long)4 * C_ * N_, nullptr, nullptr);

        float* tmp = hcur; hcur = hnxt; hnxt = tmp;
    }
}